// round 4
// baseline (speedup 1.0000x reference)
#include <cuda_runtime.h>

// ---------------------------------------------------------------------------
// Seq2seq LSTM, persistent kernel, 148 CTAs (1/SM), software grid barrier.
// Round 2: conflict-free smem fragment layouts (LDS.128 at HW-minimum
// wavefronts), cp.async double-buffered K-chunk pipeline, encoder retiled.
// ---------------------------------------------------------------------------

#define HID   256
#define BATCH 256
#define TLEN  512
#define NS    16
#define SBAT  (NS * BATCH)   // 4096
#define HOR   64
#define GRID  148
#define NTHR  256

#define STAGE_BYTES 65536                 // A slot (32KB max) + W slot (32KB)
#define GSM_OFF     (2 * STAGE_BYTES)
#define SMEM_BYTES  (GSM_OFF + 64 * 64 * 4)   // 147456

// ---------------- device scratch (no allocation allowed) -------------------
__device__ float g_eh0[2][BATCH * HID];
__device__ float g_ec0[BATCH * HID];
__device__ float g_eh1[2][BATCH * HID];
__device__ float g_ec1[BATCH * HID];

__device__ float g_dh0[2][SBAT * HID];
__device__ float g_dc0[SBAT * HID];
__device__ float g_dh1[2][SBAT * HID];
__device__ float g_dc1[SBAT * HID];
__device__ float g_dinp[SBAT];

__device__ unsigned g_cnt = 0;
__device__ volatile unsigned g_gen = 0;

// ---------------- grid-wide barrier (all CTAs resident) --------------------
__device__ __forceinline__ void gsync() {
    __syncthreads();
    if (threadIdx.x == 0) {
        __threadfence();
        unsigned old = g_gen;
        unsigned arrived = atomicAdd(&g_cnt, 1u);
        if (arrived == gridDim.x - 1) {
            g_cnt = 0;
            __threadfence();
            g_gen = old + 1u;
        } else {
            while (g_gen == old) { }
            __threadfence();
        }
    }
    __syncthreads();
}

// ---------------- packed f32x2 FMA -----------------------------------------
union F2U { float2 f; unsigned long long u; };

__device__ __forceinline__ float2 ffma2(float2 a, float2 b, float2 c) {
    F2U ua, ub, uc;
    ua.f = a; ub.f = b; uc.f = c;
    asm("fma.rn.f32x2 %0, %1, %2, %0;" : "+l"(uc.u) : "l"(ua.u), "l"(ub.u));
    return uc.f;
}

__device__ __forceinline__ float sigm(float x) {
    return 1.0f / (1.0f + expf(-x));
}

// ---------------- cp.async helpers -----------------------------------------
__device__ __forceinline__ void cpa16(void* dst, const void* src) {
    unsigned d = (unsigned)__cvta_generic_to_shared(dst);
    asm volatile("cp.async.cg.shared.global [%0], [%1], 16;" :: "r"(d), "l"(src));
}
__device__ __forceinline__ void cp_commit() {
    asm volatile("cp.async.commit_group;" ::: "memory");
}
__device__ __forceinline__ void cp_wait0() {
    asm volatile("cp.async.wait_group 0;" ::: "memory");
}
__device__ __forceinline__ void cp_wait1() {
    asm volatile("cp.async.wait_group 1;" ::: "memory");
}

// ---------------------------------------------------------------------------
// Fragment layouts per K-chunk (KC = 128 = 32 k-quads):
//   Af[q * TB + r]             : float4 = A[b0+r][kc+4q .. kc+4q+3]
//   Wf[q * TC + perm(c)]       : float4 = W[row(c)][kc+4q .. kc+4q+3]
//       perm(c) = (c&3)*16 + (c>>2)  -> LDS of lanes 0..15 is 256B contiguous
// Thread map: 16x16 (ty = tid>>4 -> RB rows, tx = tid&15 -> 4 cols).
// ---------------------------------------------------------------------------
template<int TB, int TC>
__device__ __forceinline__ void issue_chunk(
    char* stage, const float* __restrict__ A, const float* __restrict__ W,
    int b0, int j0, int kcol)
{
    constexpr int TJ = TC / 4;
    const int tid = threadIdx.x;
    float4* Af = (float4*)stage;
    float4* Wf = (float4*)(stage + 32768);
#pragma unroll
    for (int i = tid; i < TB * 32; i += NTHR) {
        int r = i >> 5, q = i & 31;
        cpa16(Af + q * TB + r, A + (size_t)(b0 + r) * HID + kcol + q * 4);
    }
#pragma unroll
    for (int i = tid; i < TC * 32; i += NTHR) {
        int c = i >> 5, q = i & 31;
        int gate = c / TJ, jj = c - gate * TJ;
        int slot = (c & 3) * 16 + (c >> 2);
        cpa16(Wf + q * TC + slot,
              W + (size_t)(gate * HID + j0 + jj) * HID + kcol + q * 4);
    }
}

template<int TB, int TC>
__device__ __forceinline__ void compute_chunk(
    const char* stage, float2 (&acc)[TB / 16][4], int ty, int tx)
{
    constexpr int RB = TB / 16;
    const float4* __restrict__ Af = (const float4*)stage;
    const float4* __restrict__ Wf = (const float4*)(stage + 32768);
    const float4* ap = Af + ty * RB;
    const float4* bp = Wf + tx;
#pragma unroll 4
    for (int k4 = 0; k4 < 32; ++k4) {
        float4 a[RB], b[4];
#pragma unroll
        for (int r = 0; r < RB; ++r) a[r] = ap[r];
#pragma unroll
        for (int c = 0; c < 4; ++c) b[c] = bp[c * 16];
#pragma unroll
        for (int r = 0; r < RB; ++r)
#pragma unroll
            for (int c = 0; c < 4; ++c) {
                acc[r][c] = ffma2(make_float2(a[r].x, a[r].y),
                                  make_float2(b[c].x, b[c].y), acc[r][c]);
                acc[r][c] = ffma2(make_float2(a[r].z, a[r].w),
                                  make_float2(b[c].z, b[c].w), acc[r][c]);
            }
        ap += TB;
        bp += TC;
    }
}

// ---------------------------------------------------------------------------
// One [TB x TC] fused LSTM layer-step tile:
//   gates = A1 @ W1^T (+ A2 @ W2^T) (+ inp[b]*wih) + bias, then c/h update.
// K = 256 streamed as 2 chunks per (A,W) pair through a 2-stage cp.async
// pipeline (2 or 4 chunks total).
// ---------------------------------------------------------------------------
template<int TB, int TC>
__device__ __forceinline__ void lstm_tile(
    char* smem, int b0, int j0,
    const float* __restrict__ A1, const float* __restrict__ W1,
    const float* __restrict__ A2, const float* __restrict__ W2,
    const float* __restrict__ inp, int inp_stride,
    const float* __restrict__ wih, const float* __restrict__ bias,
    float* __restrict__ Cst, float* __restrict__ Hout)
{
    constexpr int RB = TB / 16;
    constexpr int TJ = TC / 4;
    const int tid = threadIdx.x;
    const int ty = tid >> 4, tx = tid & 15;
    float* gsm = (float*)(smem + GSM_OFF);

    // per-thread bias / Wih column prefetch (overlaps with loads)
    float bv[4], wv[4];
#pragma unroll
    for (int cc = 0; cc < 4; ++cc) {
        int c = tx * 4 + cc, gate = c / TJ, jj = c - gate * TJ;
        int grow = gate * HID + j0 + jj;
        bv[cc] = bias[grow];
        wv[cc] = wih ? wih[grow] : 0.f;
    }

    const int nch = A2 ? 4 : 2;
    const float* Ac[4] = {A1, A1, A2, A2};
    const float* Wc[4] = {W1, W1, W2, W2};
    const int    kc[4] = {0, 128, 0, 128};

    issue_chunk<TB, TC>(smem, Ac[0], Wc[0], b0, j0, kc[0]);
    cp_commit();
    issue_chunk<TB, TC>(smem + STAGE_BYTES, Ac[1], Wc[1], b0, j0, kc[1]);
    cp_commit();

    float2 acc[RB][4];
#pragma unroll
    for (int r = 0; r < RB; ++r)
#pragma unroll
        for (int c = 0; c < 4; ++c) acc[r][c] = make_float2(0.f, 0.f);

#pragma unroll
    for (int i = 0; i < 4; ++i) {
        if (i >= nch) break;
        if (i + 1 < nch) cp_wait1(); else cp_wait0();
        __syncthreads();
        compute_chunk<TB, TC>(smem + (i & 1) * STAGE_BYTES, acc, ty, tx);
        __syncthreads();
        if (i + 2 < nch) {
            issue_chunk<TB, TC>(smem + (i & 1) * STAGE_BYTES,
                                Ac[i + 2], Wc[i + 2], b0, j0, kc[i + 2]);
            cp_commit();
        }
    }

    // epilogue: pair-sum, + bias + rank-1 input term -> gsm (vector STS.128)
#pragma unroll
    for (int r = 0; r < RB; ++r) {
        int lrow = ty * RB + r;
        float iv = wih ? inp[(size_t)(b0 + lrow) * inp_stride] : 0.f;
        float4 v;
        v.x = acc[r][0].x + acc[r][0].y + bv[0] + iv * wv[0];
        v.y = acc[r][1].x + acc[r][1].y + bv[1] + iv * wv[1];
        v.z = acc[r][2].x + acc[r][2].y + bv[2] + iv * wv[2];
        v.w = acc[r][3].x + acc[r][3].y + bv[3] + iv * wv[3];
        *(float4*)(gsm + lrow * TC + tx * 4) = v;
    }
    __syncthreads();

    // gate update
#pragma unroll
    for (int idx = tid; idx < TB * TJ; idx += NTHR) {
        int lrow = idx / TJ, jj = idx - lrow * TJ;
        const float* gr = gsm + lrow * TC;
        float ig = gr[jj];
        float fg = gr[TJ + jj];
        float gg = gr[2 * TJ + jj];
        float og = gr[3 * TJ + jj];
        int gidx = (b0 + lrow) * HID + (j0 + jj);
        float cn = sigm(fg) * Cst[gidx] + sigm(ig) * tanhf(gg);
        Cst[gidx]  = cn;
        Hout[gidx] = sigm(og) * tanhf(cn);
    }
    __syncthreads();
}

// ---------------------------------------------------------------------------
__global__ void __launch_bounds__(NTHR, 1)
lstm_all(const float* __restrict__ x,
         const float* __restrict__ eWih0, const float* __restrict__ eWhh0,
         const float* __restrict__ eb0,
         const float* __restrict__ eWih1, const float* __restrict__ eWhh1,
         const float* __restrict__ eb1,
         const float* __restrict__ dWih0, const float* __restrict__ dWhh0,
         const float* __restrict__ db0,
         const float* __restrict__ dWih1, const float* __restrict__ dWhh1,
         const float* __restrict__ db1,
         const float* __restrict__ outW, const float* __restrict__ outb,
         const float* __restrict__ dinit,
         float* __restrict__ out)
{
    extern __shared__ char smem[];
    const int tid = threadIdx.x;

    // ---- zero-init encoder state (read buffers = index 0) ----
    for (int i = blockIdx.x * NTHR + tid; i < BATCH * HID; i += GRID * NTHR) {
        g_eh0[0][i] = 0.f; g_ec0[i] = 0.f;
        g_eh1[0][i] = 0.f; g_ec1[i] = 0.f;
    }
    gsync();

    // =========================== encoder ===================================
    // TB=32, TC=64 -> 8 bt x 16 jt = 128 tiles (1 per CTA)
    for (int t = 0; t < TLEN; ++t) {
        const int rp = t & 1, wp = rp ^ 1;
        for (int tile = blockIdx.x; tile < 128; tile += GRID) {
            int bt = tile & 7, jt = tile >> 3;
            lstm_tile<32, 64>(smem, bt * 32, jt * 16,
                              g_eh0[rp], eWhh0, nullptr, nullptr,
                              x + t, TLEN, eWih0, eb0,
                              g_ec0, g_eh0[wp]);
        }
        gsync();
        for (int tile = blockIdx.x; tile < 128; tile += GRID) {
            int bt = tile & 7, jt = tile >> 3;
            lstm_tile<32, 64>(smem, bt * 32, jt * 16,
                              g_eh0[wp], eWih1, g_eh1[rp], eWhh1,
                              nullptr, 0, nullptr, eb1,
                              g_ec1, g_eh1[wp]);
        }
        gsync();
    }

    // ---- decoder init: broadcast final encoder state (buffers index 0) ----
    for (int i = blockIdx.x * NTHR + tid; i < SBAT * HID; i += GRID * NTHR) {
        int b = (i >> 8) & 255;
        int k = i & 255;
        int src = b * HID + k;
        g_dh0[0][i] = g_eh0[0][src];
        g_dc0[i]    = g_ec0[src];
        g_dh1[0][i] = g_eh1[0][src];
        g_dc1[i]    = g_ec1[src];
    }
    for (int i = blockIdx.x * NTHR + tid; i < SBAT; i += GRID * NTHR)
        g_dinp[i] = dinit[i];
    gsync();

    // =========================== decoder ===================================
    // TB=64, TC=64 -> 64 bt x 16 jt = 1024 tiles (~7 per CTA)
    const int warp = tid >> 5, lane = tid & 31;
    for (int t = 0; t < HOR; ++t) {
        const int rp = t & 1, wp = rp ^ 1;
        for (int tile = blockIdx.x; tile < 1024; tile += GRID) {
            int bt = tile & 63, jt = tile >> 6;
            lstm_tile<64, 64>(smem, bt * 64, jt * 16,
                              g_dh0[rp], dWhh0, nullptr, nullptr,
                              g_dinp, 1, dWih0, db0,
                              g_dc0, g_dh0[wp]);
        }
        gsync();
        for (int tile = blockIdx.x; tile < 1024; tile += GRID) {
            int bt = tile & 63, jt = tile >> 6;
            lstm_tile<64, 64>(smem, bt * 64, jt * 16,
                              g_dh0[wp], dWih1, g_dh1[rp], dWhh1,
                              nullptr, 0, nullptr, db1,
                              g_dc1, g_dh1[wp]);
        }
        gsync();
        // ---- pred = h1 @ outW^T + outb ; feeds next step + output ----
        const float* h1w = g_dh1[wp];
        for (int row = blockIdx.x * 8 + warp; row < SBAT; row += GRID * 8) {
            const float* hr = h1w + (size_t)row * HID;
            float s = 0.f;
#pragma unroll
            for (int kb = 0; kb < 2; ++kb) {
                int kk = kb * 128 + lane * 4;
                float4 hv = *reinterpret_cast<const float4*>(hr + kk);
                float4 wv = *reinterpret_cast<const float4*>(outW + kk);
                s += hv.x * wv.x + hv.y * wv.y + hv.z * wv.z + hv.w * wv.w;
            }
#pragma unroll
            for (int off = 16; off; off >>= 1)
                s += __shfl_xor_sync(0xffffffffu, s, off);
            if (lane == 0) {
                float p = s + outb[0];
                g_dinp[row] = p;
                int b = row & 255, sidx = row >> 8;
                out[(size_t)b * (NS * HOR) + sidx * HOR + t] = p;
            }
        }
        gsync();
    }
}

// ---------------------------------------------------------------------------
extern "C" void kernel_launch(void* const* d_in, const int* in_sizes, int n_in,
                              void* d_out, int out_size)
{
    (void)in_sizes; (void)n_in; (void)out_size;
    const float* x     = (const float*)d_in[0];
    const float* eWih0 = (const float*)d_in[1];
    const float* eWhh0 = (const float*)d_in[2];
    const float* eb0   = (const float*)d_in[3];
    const float* eWih1 = (const float*)d_in[4];
    const float* eWhh1 = (const float*)d_in[5];
    const float* eb1   = (const float*)d_in[6];
    const float* dWih0 = (const float*)d_in[7];
    const float* dWhh0 = (const float*)d_in[8];
    const float* db0   = (const float*)d_in[9];
    const float* dWih1 = (const float*)d_in[10];
    const float* dWhh1 = (const float*)d_in[11];
    const float* db1   = (const float*)d_in[12];
    const float* outW  = (const float*)d_in[13];
    const float* outb  = (const float*)d_in[14];
    const float* dinit = (const float*)d_in[15];
    float* out = (float*)d_out;

    cudaFuncSetAttribute(lstm_all, cudaFuncAttributeMaxDynamicSharedMemorySize,
                         SMEM_BYTES);

    lstm_all<<<GRID, NTHR, SMEM_BYTES>>>(x, eWih0, eWhh0, eb0, eWih1, eWhh1, eb1,
                                         dWih0, dWhh0, db0, dWih1, dWhh1, db1,
                                         outW, outb, dinit, out);
}

// round 5
// speedup vs baseline: 1.2199x; 1.2199x over previous
#include <cuda_runtime.h>

// ---------------------------------------------------------------------------
// Seq2seq LSTM, ONE persistent kernel, GRID=128 CTAs (1/SM), software barrier.
// - Weights RESIDENT in smem (192KB/CTA, loaded once per segment)
// - Gate-spread thread mapping -> register-only LSTM cell epilogue
// - Flat 2-stage cp.async chunk ring across tiles (no cold starts)
// - Skewed encoder phases {L0(t), L1(t-1)} -> 513 barriers
// - Decoder projection fused into L1 epilogue (shfl + atomicAdd) -> 2 bar/step
// ---------------------------------------------------------------------------

#define HID   256
#define BATCH 256
#define TLEN  512
#define NS    16
#define SBAT  4096
#define HOR   64
#define GRID  128
#define NTHR  256

#define W_REG_BYTES 65536
#define A_OFF       196608
#define A_STAGE     16384
#define SMEM_BYTES  229376     // 3*64KB W + 2*16KB A stages

// ---------------- device state (no allocation allowed) ---------------------
__device__ float g_eh0[2][BATCH * HID];
__device__ float g_ec0[BATCH * HID];
__device__ float g_eh1[2][BATCH * HID];
__device__ float g_ec1[BATCH * HID];

__device__ float g_dh0[2][SBAT * HID];
__device__ float g_dc0[SBAT * HID];
__device__ float g_dh1[2][SBAT * HID];
__device__ float g_dc1[SBAT * HID];
__device__ float g_pred[2][SBAT];

__device__ unsigned g_cnt = 0;
__device__ volatile unsigned g_gen = 0;

// ---------------- grid-wide barrier -----------------------------------------
__device__ __forceinline__ void gsync() {
    __syncthreads();
    if (threadIdx.x == 0) {
        __threadfence();
        unsigned old = g_gen;
        unsigned arrived = atomicAdd(&g_cnt, 1u);
        if (arrived == gridDim.x - 1) {
            g_cnt = 0;
            __threadfence();
            g_gen = old + 1u;
        } else {
            while (g_gen == old) { }
            __threadfence();
        }
    }
    __syncthreads();
}

// ---------------- packed f32x2 FMA ------------------------------------------
union F2U { float2 f; unsigned long long u; };

__device__ __forceinline__ float2 ffma2(float2 a, float2 b, float2 c) {
    F2U ua, ub, uc;
    ua.f = a; ub.f = b; uc.f = c;
    asm("fma.rn.f32x2 %0, %1, %2, %0;" : "+l"(uc.u) : "l"(ua.u), "l"(ub.u));
    return uc.f;
}

__device__ __forceinline__ float sigm(float x) {
    return 1.0f / (1.0f + expf(-x));
}

// ---------------- cp.async helpers -----------------------------------------
__device__ __forceinline__ void cpa16(void* dst, const void* src) {
    unsigned d = (unsigned)__cvta_generic_to_shared(dst);
    asm volatile("cp.async.cg.shared.global [%0], [%1], 16;" :: "r"(d), "l"(src));
}
__device__ __forceinline__ void cp_commit() {
    asm volatile("cp.async.commit_group;" ::: "memory");
}
__device__ __forceinline__ void cp_wait0() {
    asm volatile("cp.async.wait_group 0;" ::: "memory");
}
__device__ __forceinline__ void cp_wait1() {
    asm volatile("cp.async.wait_group 1;" ::: "memory");
}

// ---------------------------------------------------------------------------
// Resident W region: Wf[k4*64 + slot], slot = gate*16 + jj (jj = local j).
// 64 rows x 256 K x 4B = 64KB per region. k4-fast loading -> coalesced 1KB/row.
// ---------------------------------------------------------------------------
__device__ __forceinline__ void load_W_region(char* dst, const float* __restrict__ W,
                                              int j0, int tid) {
    float4* Wf = (float4*)dst;
#pragma unroll
    for (int i = tid; i < 4096; i += NTHR) {
        int k4 = i & 63;
        int s  = i >> 6;
        int gate = s >> 4, jj = s & 15;
        cpa16(&Wf[k4 * 64 + s], W + (size_t)(gate * HID + j0 + jj) * HID + k4 * 4);
    }
}

// A chunk loaders. Layout Af[q*TB + r] (row-fragment float4 = 4 consecutive k).
__device__ __forceinline__ void issue_A32(char* stage, const float* __restrict__ A,
                                          int kc, int tid) {  // TB=32, Kchunk=128
    float4* Af = (float4*)stage;
#pragma unroll
    for (int i = tid; i < 1024; i += NTHR) {
        int r = i >> 5, q = i & 31;
        cpa16(&Af[q * 32 + r], A + (size_t)r * HID + kc + q * 4);
    }
}
__device__ __forceinline__ void issue_A128(char* stage, const float* __restrict__ A,
                                           int kc, int tid) { // TB=128, Kchunk=32
    float4* Af = (float4*)stage;
#pragma unroll
    for (int i = tid; i < 1024; i += NTHR) {
        int r = i >> 3, q = i & 7;
        cpa16(&Af[q * 128 + r], A + (size_t)r * HID + kc + q * 4);
    }
}

// ---------------------------------------------------------------------------
// GEMM over one chunk. Thread (ty,tx): rows ty+16r (r<RB), col j0+tx, 4 gates.
//   a[r] = Af[k4*TB + ty + 16r]        (1 wavefront per LDS.128)
//   b[c] = Wfc[k4*64 + c*16 + tx]      (2 wavefronts, HW minimum)
// ---------------------------------------------------------------------------
template<int TB, int NK4>
__device__ __forceinline__ void gemm_chunk(const char* stage,
                                           const float4* __restrict__ Wfc,
                                           float2 (&acc)[TB / 16][4],
                                           int ty, int tx)
{
    constexpr int RB = TB / 16;
    const float4* __restrict__ Af = (const float4*)stage;
#pragma unroll 4
    for (int k4 = 0; k4 < NK4; ++k4) {
        const float4* ap = Af + k4 * TB + ty;
        const float4* bp = Wfc + k4 * 64 + tx;
        float4 b4[4];
#pragma unroll
        for (int c = 0; c < 4; ++c) b4[c] = bp[c * 16];
        float4 a4[RB];
#pragma unroll
        for (int r = 0; r < RB; ++r) a4[r] = ap[r * 16];
#pragma unroll
        for (int r = 0; r < RB; ++r)
#pragma unroll
            for (int c = 0; c < 4; ++c) {
                acc[r][c] = ffma2(make_float2(a4[r].x, a4[r].y),
                                  make_float2(b4[c].x, b4[c].y), acc[r][c]);
                acc[r][c] = ffma2(make_float2(a4[r].z, a4[r].w),
                                  make_float2(b4[c].z, b4[c].w), acc[r][c]);
            }
    }
}

// ---------------------------------------------------------------------------
__global__ void __launch_bounds__(NTHR, 1)
lstm_all(const float* __restrict__ x,
         const float* __restrict__ eWih0, const float* __restrict__ eWhh0,
         const float* __restrict__ eb0,
         const float* __restrict__ eWih1, const float* __restrict__ eWhh1,
         const float* __restrict__ eb1,
         const float* __restrict__ dWih0, const float* __restrict__ dWhh0,
         const float* __restrict__ db0,
         const float* __restrict__ dWih1, const float* __restrict__ dWhh1,
         const float* __restrict__ db1,
         const float* __restrict__ outW, const float* __restrict__ outb,
         const float* __restrict__ dinit,
         float* __restrict__ out)
{
    extern __shared__ char smem[];
    const int tid = threadIdx.x;
    const int ty = tid >> 4, tx = tid & 15;
    const int jt = blockIdx.x >> 3;           // 0..15, fixed j-tile
    const int j0 = jt * 16;
    const int ebt = blockIdx.x & 7;           // encoder batch tile
    const int eRow0 = ebt * 32;
    const int gI = blockIdx.x & 7;            // decoder row group
    const int dRow0base = gI * 512;

    const float4* W0f = (const float4*)(smem);
    const float4* W1f = (const float4*)(smem + W_REG_BYTES);
    const float4* W2f = (const float4*)(smem + 2 * W_REG_BYTES);
    char* st0 = smem + A_OFF;
    char* st1 = smem + A_OFF + A_STAGE;

    // ---- per-thread constants (fixed j column) ----
    float e_bv0[4], e_wv0[4], e_bv1[4];
#pragma unroll
    for (int c = 0; c < 4; ++c) {
        int gr = c * HID + j0 + tx;
        e_bv0[c] = eb0[gr];
        e_wv0[c] = eWih0[gr];   // in_features = 1
        e_bv1[c] = eb1[gr];
    }

    // ---- resident encoder weights + zero-init state ----
    load_W_region(smem,                  eWhh0, j0, tid);
    load_W_region(smem + W_REG_BYTES,    eWih1, j0, tid);
    load_W_region(smem + 2 * W_REG_BYTES, eWhh1, j0, tid);
    cp_commit();
    for (int i = blockIdx.x * NTHR + tid; i < BATCH * HID; i += GRID * NTHR) {
        g_eh0[1][i] = 0.f; g_ec0[i] = 0.f;
        g_eh1[1][i] = 0.f; g_ec1[i] = 0.f;
    }
    cp_wait0();
    gsync();

    // =========================== encoder (skewed) ==========================
    // phase p: layer0(t=p) [p<TLEN], layer1(t'=p-1) [p>0]; 6 chunks max.
    for (int p = 0; p <= TLEN; ++p) {
        const float* hA  = g_eh0[(p + 1) & 1] + (size_t)eRow0 * HID; // h0(p-1)
        const float* h1r = g_eh1[p & 1]       + (size_t)eRow0 * HID; // h1(p-2)

        const float* Ab[6]; int kcs[6]; const float4* Wr[6];
        int n = 0, n0 = 0;
        if (p < TLEN) {
            Ab[0] = hA; kcs[0] = 0;   Wr[0] = W0f;
            Ab[1] = hA; kcs[1] = 128; Wr[1] = W0f;
            n = n0 = 2;
        }
        if (p > 0) {
            Ab[n] = hA;  kcs[n] = 0;   Wr[n] = W1f; ++n;
            Ab[n] = hA;  kcs[n] = 128; Wr[n] = W1f; ++n;
            Ab[n] = h1r; kcs[n] = 0;   Wr[n] = W2f; ++n;
            Ab[n] = h1r; kcs[n] = 128; Wr[n] = W2f; ++n;
        }

        float2 acc0[2][4], acc1[2][4];
#pragma unroll
        for (int r = 0; r < 2; ++r)
#pragma unroll
            for (int c = 0; c < 4; ++c) {
                acc0[r][c] = make_float2(0.f, 0.f);
                acc1[r][c] = make_float2(0.f, 0.f);
            }

        issue_A32(st0, Ab[0], kcs[0], tid); cp_commit();
        if (n > 1) { issue_A32(st1, Ab[1], kcs[1], tid); cp_commit(); }

        for (int i = 0; i < n; ++i) {
            if (i + 1 < n) cp_wait1(); else cp_wait0();
            __syncthreads();
            char* st = (i & 1) ? st1 : st0;
            if (i < n0) gemm_chunk<32, 32>(st, Wr[i] + (kcs[i] >> 2) * 64, acc0, ty, tx);
            else        gemm_chunk<32, 32>(st, Wr[i] + (kcs[i] >> 2) * 64, acc1, ty, tx);
            __syncthreads();
            if (i + 2 < n) { issue_A32(st, Ab[i + 2], kcs[i + 2], tid); cp_commit(); }

            if (i == n0 - 1 && p < TLEN) {
                // layer0 epilogue, t = p
#pragma unroll
                for (int r = 0; r < 2; ++r) {
                    int row = eRow0 + ty + 16 * r;
                    float xv = x[(size_t)row * TLEN + p];
                    float gi = acc0[r][0].x + acc0[r][0].y + e_bv0[0] + xv * e_wv0[0];
                    float gf = acc0[r][1].x + acc0[r][1].y + e_bv0[1] + xv * e_wv0[1];
                    float gg = acc0[r][2].x + acc0[r][2].y + e_bv0[2] + xv * e_wv0[2];
                    float go = acc0[r][3].x + acc0[r][3].y + e_bv0[3] + xv * e_wv0[3];
                    int idx = row * HID + j0 + tx;
                    float cn = sigm(gf) * g_ec0[idx] + sigm(gi) * tanhf(gg);
                    g_ec0[idx] = cn;
                    g_eh0[p & 1][idx] = sigm(go) * tanhf(cn);
                }
            }
            if (i == n - 1 && p > 0) {
                // layer1 epilogue, t' = p-1
#pragma unroll
                for (int r = 0; r < 2; ++r) {
                    int row = eRow0 + ty + 16 * r;
                    float gi = acc1[r][0].x + acc1[r][0].y + e_bv1[0];
                    float gf = acc1[r][1].x + acc1[r][1].y + e_bv1[1];
                    float gg = acc1[r][2].x + acc1[r][2].y + e_bv1[2];
                    float go = acc1[r][3].x + acc1[r][3].y + e_bv1[3];
                    int idx = row * HID + j0 + tx;
                    float cn = sigm(gf) * g_ec1[idx] + sigm(gi) * tanhf(gg);
                    g_ec1[idx] = cn;
                    g_eh1[(p + 1) & 1][idx] = sigm(go) * tanhf(cn);
                }
            }
        }
        gsync();
    }

    // ============== decoder setup: W reload + state broadcast ===============
    load_W_region(smem,                   dWhh0, j0, tid);
    load_W_region(smem + W_REG_BYTES,     dWih1, j0, tid);
    load_W_region(smem + 2 * W_REG_BYTES, dWhh1, j0, tid);
    cp_commit();
    for (int i = blockIdx.x * NTHR + tid; i < SBAT * HID; i += GRID * NTHR) {
        int src = i & (BATCH * HID - 1);
        g_dh0[1][i] = g_eh0[1][src];
        g_dc0[i]    = g_ec0[src];
        g_dh1[1][i] = g_eh1[1][src];
        g_dc1[i]    = g_ec1[src];
    }
    cp_wait0();
    gsync();

    float d_bv0[4], d_wv0[4], d_bv1[4];
#pragma unroll
    for (int c = 0; c < 4; ++c) {
        int gr = c * HID + j0 + tx;
        d_bv0[c] = db0[gr];
        d_wv0[c] = dWih0[gr];
        d_bv1[c] = db1[gr];
    }
    const float outw  = outW[j0 + tx];
    const float outbv = outb[0];

    // =========================== decoder ====================================
    for (int t = 0; t < HOR; ++t) {
        const int rp = (t + 1) & 1, wp = t & 1;

        // ---- layer0 phase: 4 tiles x 8 chunks (K=32) ----
        if (tid < 32) g_pred[wp][blockIdx.x * 32 + tid] = 0.f;   // zero accum buf
        {
            const float* h0r = g_dh0[rp];
            float2 acc[8][4];
            issue_A128(st0, h0r + (size_t)dRow0base * HID, 0, tid); cp_commit();
            issue_A128(st1, h0r + (size_t)dRow0base * HID, 32, tid); cp_commit();
            for (int i = 0; i < 32; ++i) {
                if ((i & 7) == 0) {
#pragma unroll
                    for (int r = 0; r < 8; ++r)
#pragma unroll
                        for (int c = 0; c < 4; ++c) acc[r][c] = make_float2(0.f, 0.f);
                }
                if (i + 1 < 32) cp_wait1(); else cp_wait0();
                __syncthreads();
                char* st = (i & 1) ? st1 : st0;
                gemm_chunk<128, 8>(st, W0f + (i & 7) * 8 * 64, acc, ty, tx);
                __syncthreads();
                if (i + 2 < 32) {
                    int ni = i + 2;
                    issue_A128(st, h0r + (size_t)(dRow0base + (ni >> 3) * 128) * HID,
                               (ni & 7) * 32, tid);
                    cp_commit();
                }
                if ((i & 7) == 7) {
                    int b0row = dRow0base + (i >> 3) * 128;
#pragma unroll
                    for (int r = 0; r < 8; ++r) {
                        int row = b0row + ty + 16 * r;
                        float iv;
                        if (t == 0) {
                            iv = dinit[row];
                        } else {
                            iv = __ldcg(&g_pred[rp][row]) + outbv;
                            if (jt == 0 && tx == 0)
                                out[(size_t)(row & 255) * (NS * HOR)
                                    + (row >> 8) * HOR + (t - 1)] = iv;
                        }
                        float gi = acc[r][0].x + acc[r][0].y + d_bv0[0] + iv * d_wv0[0];
                        float gf = acc[r][1].x + acc[r][1].y + d_bv0[1] + iv * d_wv0[1];
                        float gg = acc[r][2].x + acc[r][2].y + d_bv0[2] + iv * d_wv0[2];
                        float go = acc[r][3].x + acc[r][3].y + d_bv0[3] + iv * d_wv0[3];
                        int idx = row * HID + j0 + tx;
                        float cn = sigm(gf) * g_dc0[idx] + sigm(gi) * tanhf(gg);
                        g_dc0[idx] = cn;
                        g_dh0[wp][idx] = sigm(go) * tanhf(cn);
                    }
                }
            }
        }
        gsync();

        // ---- layer1 phase: 4 tiles x 16 chunks (Wih1 on h0cur + Whh1 on h1prev) ----
        {
            const float* h0c = g_dh0[wp];
            const float* h1r = g_dh1[rp];
            float2 acc[8][4];
            issue_A128(st0, h0c + (size_t)dRow0base * HID, 0, tid); cp_commit();
            issue_A128(st1, h0c + (size_t)dRow0base * HID, 32, tid); cp_commit();
            for (int i = 0; i < 64; ++i) {
                if ((i & 15) == 0) {
#pragma unroll
                    for (int r = 0; r < 8; ++r)
#pragma unroll
                        for (int c = 0; c < 4; ++c) acc[r][c] = make_float2(0.f, 0.f);
                }
                if (i + 1 < 64) cp_wait1(); else cp_wait0();
                __syncthreads();
                char* st = (i & 1) ? st1 : st0;
                const float4* wb = (((i & 15) < 8) ? W1f : W2f) + (i & 7) * 8 * 64;
                gemm_chunk<128, 8>(st, wb, acc, ty, tx);
                __syncthreads();
                if (i + 2 < 64) {
                    int ni = i + 2;
                    const float* Abase = (((ni & 15) < 8) ? h0c : h1r);
                    issue_A128(st, Abase + (size_t)(dRow0base + (ni >> 4) * 128) * HID,
                               (ni & 7) * 32, tid);
                    cp_commit();
                }
                if ((i & 15) == 15) {
                    int b0row = dRow0base + (i >> 4) * 128;
#pragma unroll
                    for (int r = 0; r < 8; ++r) {
                        int row = b0row + ty + 16 * r;
                        float gi = acc[r][0].x + acc[r][0].y + d_bv1[0];
                        float gf = acc[r][1].x + acc[r][1].y + d_bv1[1];
                        float gg = acc[r][2].x + acc[r][2].y + d_bv1[2];
                        float go = acc[r][3].x + acc[r][3].y + d_bv1[3];
                        int idx = row * HID + j0 + tx;
                        float cn = sigm(gf) * g_dc1[idx] + sigm(gi) * tanhf(gg);
                        g_dc1[idx] = cn;
                        float h = sigm(go) * tanhf(cn);
                        g_dh1[wp][idx] = h;
                        // fused projection partial: sum over this CTA's 16 j's
                        float part = h * outw;
                        part += __shfl_xor_sync(0xffffffffu, part, 1);
                        part += __shfl_xor_sync(0xffffffffu, part, 2);
                        part += __shfl_xor_sync(0xffffffffu, part, 4);
                        part += __shfl_xor_sync(0xffffffffu, part, 8);
                        if (tx == 0) atomicAdd(&g_pred[wp][row], part);
                    }
                }
            }
        }
        gsync();
    }

    // ---- tail: write out for t = HOR-1 ----
    if (tid < 32) {
        int row = blockIdx.x * 32 + tid;
        float v = __ldcg(&g_pred[(HOR - 1) & 1][row]) + outbv;
        out[(size_t)(row & 255) * (NS * HOR) + (row >> 8) * HOR + (HOR - 1)] = v;
    }
}

// ---------------------------------------------------------------------------
extern "C" void kernel_launch(void* const* d_in, const int* in_sizes, int n_in,
                              void* d_out, int out_size)
{
    (void)in_sizes; (void)n_in; (void)out_size;
    const float* x     = (const float*)d_in[0];
    const float* eWih0 = (const float*)d_in[1];
    const float* eWhh0 = (const float*)d_in[2];
    const float* eb0   = (const float*)d_in[3];
    const float* eWih1 = (const float*)d_in[4];
    const float* eWhh1 = (const float*)d_in[5];
    const float* eb1   = (const float*)d_in[6];
    const float* dWih0 = (const float*)d_in[7];
    const float* dWhh0 = (const float*)d_in[8];
    const float* db0   = (const float*)d_in[9];
    const float* dWih1 = (const float*)d_in[10];
    const float* dWhh1 = (const float*)d_in[11];
    const float* db1   = (const float*)d_in[12];
    const float* outW  = (const float*)d_in[13];
    const float* outb  = (const float*)d_in[14];
    const float* dinit = (const float*)d_in[15];
    float* out = (float*)d_out;

    cudaFuncSetAttribute(lstm_all, cudaFuncAttributeMaxDynamicSharedMemorySize,
                         SMEM_BYTES);

    lstm_all<<<GRID, NTHR, SMEM_BYTES>>>(x, eWih0, eWhh0, eb0, eWih1, eWhh1, eb1,
                                         dWih0, dWhh0, db0, dWih1, dWhh1, db1,
                                         outW, outb, dinit, out);
}